// round 1
// baseline (speedup 1.0000x reference)
#include <cuda_runtime.h>

#define NH   128
#define LVL  7
#define W0S  56.0f

// Pre-transposed weights (k-major) and pre-scaled grid matrices.
__device__ float g_WmT[LVL * NH * NH];
__device__ float g_WhT[LVL * NH * NH];
__device__ float g_As [LVL * 2 * NH];

__global__ void prep_kernel(const float* __restrict__ Wm,
                            const float* __restrict__ Wh,
                            const float* __restrict__ A,
                            const float* __restrict__ sigma) {
    int stride = gridDim.x * blockDim.x;
    int i0 = blockIdx.x * blockDim.x + threadIdx.x;
    for (int o = i0; o < LVL * NH * NH; o += stride) {
        int l = o >> 14;
        int r = (o >> 7) & 127;   // k
        int c = o & 127;          // n
        g_WmT[o] = Wm[(l << 14) + (c << 7) + r];
        g_WhT[o] = Wh[(l << 14) + (c << 7) + r];
    }
    for (int o = i0; o < LVL * 2 * NH; o += stride) {
        int l = o >> 8;
        g_As[o] = A[o] * (6.28318530717958647692f * sigma[l]);
    }
}

// Store one xT row (row n, 8 m-values owned by this thread) with XOR swizzle.
__device__ __forceinline__ void store_x_row(float* xT, int n, int tm, const float v[8]) {
    int key = n >> 3;
    int c0 = (((tm << 1)      ^ key) & 31) << 2;
    int c1 = ((((tm << 1) | 1) ^ key) & 31) << 2;
    *(float4*)(xT + n * NH + c0) = make_float4(v[0], v[1], v[2], v[3]);
    *(float4*)(xT + n * NH + c1) = make_float4(v[4], v[5], v[6], v[7]);
}

// 128x128x128-per-CTA GEMM: acc[m 8][n-pair 4] += xT[k][m] * W[n][k]
// W in smem is k-major: sW[k*128 + n]. x rows are XOR-swizzled by (k>>3).
__device__ __forceinline__ void gemm128(const float* __restrict__ xT,
                                        const float* __restrict__ sW,
                                        int tm, int tn,
                                        unsigned long long acc[8][4]) {
#pragma unroll 1
    for (int kb = 0; kb < 16; ++kb) {
        const float* xr = xT + kb * 1024;
        const float* wr = sW + kb * 1024 + tn * 8;
        int c0 = ((((tm << 1))     ^ kb) & 31) << 2;
        int c1 = ((((tm << 1) | 1) ^ kb) & 31) << 2;
#pragma unroll
        for (int kk = 0; kk < 8; ++kk) {
            float4 xa = *(const float4*)(xr + kk * NH + c0);
            float4 xb = *(const float4*)(xr + kk * NH + c1);
            ulonglong2 wA = *(const ulonglong2*)(wr + kk * NH);
            ulonglong2 wB = *(const ulonglong2*)(wr + kk * NH + 4);
            float xs[8] = {xa.x, xa.y, xa.z, xa.w, xb.x, xb.y, xb.z, xb.w};
#pragma unroll
            for (int i = 0; i < 8; ++i) {
                unsigned long long xd;
                asm("mov.b64 %0, {%1,%1};" : "=l"(xd) : "f"(xs[i]));
                asm("fma.rn.f32x2 %0, %1, %2, %0;" : "+l"(acc[i][0]) : "l"(xd), "l"(wA.x));
                asm("fma.rn.f32x2 %0, %1, %2, %0;" : "+l"(acc[i][1]) : "l"(xd), "l"(wA.y));
                asm("fma.rn.f32x2 %0, %1, %2, %0;" : "+l"(acc[i][2]) : "l"(xd), "l"(wB.x));
                asm("fma.rn.f32x2 %0, %1, %2, %0;" : "+l"(acc[i][3]) : "l"(xd), "l"(wB.y));
            }
        }
    }
}

__device__ __forceinline__ float acc_half(unsigned long long a, int odd) {
    return odd ? __uint_as_float((unsigned)(a >> 32))
               : __uint_as_float((unsigned)a);
}

__global__ void __launch_bounds__(256, 1) ffb_main(
    const float* __restrict__ in_pos,
    const float* __restrict__ gfeat,
    const float* __restrict__ W0,
    const float* __restrict__ b0,
    const float* __restrict__ b_mid,
    const float* __restrict__ b_high,
    float* __restrict__ out) {
    extern __shared__ float sm[];
    float* xT  = sm;            // 16384 floats (swizzled)
    float* sWm = sm + 16384;    // 16384
    float* sWh = sm + 32768;    // 16384
    float* gxs = sm + 49152;    // 128*14 = 1792
    float* bms = gxs + 1792;    // 896
    float* bhs = bms + 896;     // 896
    float* Asm = bhs + 896;     // 1792

    const int tid = threadIdx.x;
    const int tm  = tid >> 4;   // 0..15 : m-block
    const int tn  = tid & 15;   // 0..15 : n-block
    const int p0  = blockIdx.x << 7;

    // Stage per-CTA grid features / biases / A matrices.
    for (int idx = tid; idx < 1792; idx += 256) {
        int m = idx / 14;
        int c = idx - m * 14;
        gxs[idx] = gfeat[(p0 + m) * 17 + 3 + c];
    }
    for (int idx = tid; idx < 896; idx += 256) {
        bms[idx] = b_mid[idx];
        bhs[idx] = b_high[idx];
    }
    for (int idx = tid; idx < 1792; idx += 256) Asm[idx] = g_As[idx];

    // pos01 part of the output.
    if (tid < 128) {
        int m = p0 + tid;
        float a = in_pos[m * 3 + 0], b = in_pos[m * 3 + 1], c = in_pos[m * 3 + 2];
        out[(long long)m * 131 + 0] = (a + 1.0f) * 0.5f;
        out[(long long)m * 131 + 1] = (b + 1.0f) * 0.5f;
        out[(long long)m * 131 + 2] = (c + 1.0f) * 0.5f;
    }

    // First SIREN layer (K=3) straight from global, store to swizzled xT.
    {
        float px[8], py[8], pz[8];
#pragma unroll
        for (int i = 0; i < 8; ++i) {
            int m = p0 + tm * 8 + i;
            px[i] = in_pos[m * 3 + 0];
            py[i] = in_pos[m * 3 + 1];
            pz[i] = in_pos[m * 3 + 2];
        }
#pragma unroll
        for (int j = 0; j < 8; ++j) {
            int n = tn * 8 + j;
            float w0 = W0[n * 3 + 0], w1 = W0[n * 3 + 1], w2 = W0[n * 3 + 2];
            float bb = b0[n];
            float v[8];
#pragma unroll
            for (int i = 0; i < 8; ++i)
                v[i] = __sinf(W0S * (px[i] * w0 + py[i] * w1 + pz[i] * w2 + bb));
            store_x_row(xT, n, tm, v);
        }
    }

    float buf[8][8];
#pragma unroll
    for (int i = 0; i < 8; ++i)
#pragma unroll
        for (int j = 0; j < 8; ++j) buf[i][j] = 0.0f;

#pragma unroll 1
    for (int l = 0; l < LVL; ++l) {
        __syncthreads();   // prev high-GEMM done reading sWh / xT; init stores visible at l=0
        {
            const float4* gm = (const float4*)(g_WmT + l * 16384);
            const float4* gh = (const float4*)(g_WhT + l * 16384);
            float4* dm = (float4*)sWm;
            float4* dh = (float4*)sWh;
#pragma unroll
            for (int t = 0; t < 16; ++t) {
                dm[tid + t * 256] = gm[tid + t * 256];
                dh[tid + t * 256] = gh[tid + t * 256];
            }
        }
        __syncthreads();

        unsigned long long acc[8][4];
#pragma unroll
        for (int i = 0; i < 8; ++i) {
            acc[i][0] = 0ULL; acc[i][1] = 0ULL; acc[i][2] = 0ULL; acc[i][3] = 0ULL;
        }
        gemm128(xT, sWm, tm, tn, acc);
        __syncthreads();   // everyone done reading old xT

        // mid epilogue: x = sin(56*(acc+b)) + sin(g·A); store new xT
        {
            float g0[8], g1[8];
#pragma unroll
            for (int i = 0; i < 8; ++i) {
                g0[i] = gxs[(tm * 8 + i) * 14 + 2 * l];
                g1[i] = gxs[(tm * 8 + i) * 14 + 2 * l + 1];
            }
#pragma unroll
            for (int j = 0; j < 8; ++j) {
                int n = tn * 8 + j;
                float bb = bms[l * 128 + n];
                float A0 = Asm[l * 256 + n];
                float A1 = Asm[l * 256 + 128 + n];
                float v[8];
#pragma unroll
                for (int i = 0; i < 8; ++i) {
                    float av = acc_half(acc[i][j >> 1], j & 1);
                    v[i] = __sinf(W0S * (av + bb)) + __sinf(fmaf(g0[i], A0, g1[i] * A1));
                }
                store_x_row(xT, n, tm, v);
            }
        }
        __syncthreads();   // new xT visible

        // high GEMM + buf accumulation
#pragma unroll
        for (int i = 0; i < 8; ++i) {
            acc[i][0] = 0ULL; acc[i][1] = 0ULL; acc[i][2] = 0ULL; acc[i][3] = 0ULL;
        }
        gemm128(xT, sWh, tm, tn, acc);

#pragma unroll
        for (int j = 0; j < 8; ++j) {
            int n = tn * 8 + j;
            float bb = bhs[l * 128 + n];
#pragma unroll
            for (int i = 0; i < 8; ++i) {
                float av = acc_half(acc[i][j >> 1], j & 1);
                buf[i][j] += __sinf(W0S * (av + bb));
            }
        }
    }

    const float inv7 = 1.0f / 7.0f;
#pragma unroll
    for (int i = 0; i < 8; ++i) {
        long long base = (long long)(p0 + tm * 8 + i) * 131 + 3 + tn * 8;
#pragma unroll
        for (int j = 0; j < 8; ++j)
            out[base + j] = buf[i][j] * inv7;
    }
}

extern "C" void kernel_launch(void* const* d_in, const int* in_sizes, int n_in,
                              void* d_out, int out_size) {
    const float* in_pos = (const float*)d_in[0];
    const float* gfeat  = (const float*)d_in[1];
    const float* ffn_A  = (const float*)d_in[2];
    const float* sigma  = (const float*)d_in[3];
    const float* W0     = (const float*)d_in[4];
    const float* b0     = (const float*)d_in[5];
    const float* W_mid  = (const float*)d_in[6];
    const float* b_mid  = (const float*)d_in[7];
    const float* W_high = (const float*)d_in[8];
    const float* b_high = (const float*)d_in[9];
    float* out = (float*)d_out;

    int N = in_sizes[0] / 3;

    prep_kernel<<<128, 256>>>(W_mid, W_high, ffn_A, sigma);

    size_t smem = (size_t)(16384 * 3 + 1792 + 896 + 896 + 1792) * sizeof(float); // 218112 B
    cudaFuncSetAttribute(ffb_main, cudaFuncAttributeMaxDynamicSharedMemorySize, (int)smem);
    ffb_main<<<N / 128, 256, smem>>>(in_pos, gfeat, W0, b0, b_mid, b_high, out);
}

// round 3
// speedup vs baseline: 1.9147x; 1.9147x over previous
#include <cuda_runtime.h>
#include <cuda_bf16.h>
#include <cstdint>

#define LVL  7
#define W0S  56.0f

// SMEM byte offsets
#define SOFF_XH   0
#define SOFF_XL   32768
#define SOFF_WMH  65536
#define SOFF_WML  98304
#define SOFF_WHH  131072
#define SOFF_WHL  163840
#define SOFF_GXS  196608   // 1792 floats
#define SOFF_BMS  203776   // 896 floats
#define SOFF_BHS  207360   // 896 floats
#define SOFF_ASM  210944   // 1792 floats
#define SMEM_TOTAL 218112

// Pre-split, pre-swizzled bf16 weight tiles (n-major: W[n][k]).
__device__ __align__(16) char g_Wmh[LVL * 32768];
__device__ __align__(16) char g_Wml[LVL * 32768];
__device__ __align__(16) char g_Whh[LVL * 32768];
__device__ __align__(16) char g_Whl[LVL * 32768];
__device__ float g_As[LVL * 256];

// Byte offset of bf16 element (row r, col k) in a [128][128] bf16 tile.
// Row = 256B = 16 chunks of 16B; chunk index XOR (r&7) -> conflict-free
// for ldmatrix (8 rows per phase hit 8 distinct chunks = 128B).
__host__ __device__ __forceinline__ int swoff(int r, int k) {
    return (r << 8) + ((((k >> 3) ^ (r & 7)) & 15) << 4) + ((k & 7) << 1);
}

__global__ void prep_kernel(const float* __restrict__ Wm,
                            const float* __restrict__ Wh,
                            const float* __restrict__ A,
                            const float* __restrict__ sigma) {
    int i0 = blockIdx.x * blockDim.x + threadIdx.x;
    int stride = gridDim.x * blockDim.x;
    for (int idx = i0; idx < LVL * 16384; idx += stride) {
        int l = idx >> 14, rem = idx & 16383;
        int n = rem >> 7, k = rem & 127;
        int dst = l * 32768 + swoff(n, k);
        float wm = Wm[idx];
        __nv_bfloat16 hm = __float2bfloat16(wm);
        *(__nv_bfloat16*)(g_Wmh + dst) = hm;
        *(__nv_bfloat16*)(g_Wml + dst) = __float2bfloat16(wm - __bfloat162float(hm));
        float wh = Wh[idx];
        __nv_bfloat16 hh = __float2bfloat16(wh);
        *(__nv_bfloat16*)(g_Whh + dst) = hh;
        *(__nv_bfloat16*)(g_Whl + dst) = __float2bfloat16(wh - __bfloat162float(hh));
    }
    for (int idx = i0; idx < LVL * 256; idx += stride) {
        int l = idx >> 8;
        g_As[idx] = A[idx] * (6.28318530717958647692f * sigma[l]);
    }
}

__device__ __forceinline__ uint32_t smem_u32(const void* p) {
    uint32_t a;
    asm("{ .reg .u64 t; cvta.to.shared.u64 t, %1; cvt.u32.u64 %0, t; }" : "=r"(a) : "l"(p));
    return a;
}

__device__ __forceinline__ void ldsm4(uint32_t* r, uint32_t addr) {
    asm volatile("ldmatrix.sync.aligned.m8n8.x4.shared.b16 {%0,%1,%2,%3}, [%4];"
                 : "=r"(r[0]), "=r"(r[1]), "=r"(r[2]), "=r"(r[3]) : "r"(addr));
}

__device__ __forceinline__ void mma16816(float* d, const uint32_t* a, const uint32_t* b) {
    asm volatile(
        "mma.sync.aligned.m16n8k16.row.col.f32.bf16.bf16.f32 "
        "{%0,%1,%2,%3}, {%4,%5,%6,%7}, {%8,%9}, {%0,%1,%2,%3};"
        : "+f"(d[0]), "+f"(d[1]), "+f"(d[2]), "+f"(d[3])
        : "r"(a[0]), "r"(a[1]), "r"(a[2]), "r"(a[3]), "r"(b[0]), "r"(b[1]));
}

// lane address for A-tile ldmatrix.x4 covering (r0..r0+15, k0..k0+15)
__device__ __forceinline__ uint32_t addrA(uint32_t base, int lane, int r0, int k0) {
    int sub = lane >> 3;
    int row = r0 + (lane & 7) + ((sub & 1) << 3);
    int kk  = k0 + ((sub & 2) << 2);
    return base + (row << 8) + ((((kk >> 3) ^ (row & 7)) & 15) << 4);
}

// lane address for B-tile ldmatrix.x4 covering (n0..n0+15, k0..k0+15)
__device__ __forceinline__ uint32_t addrB(uint32_t base, int lane, int n0, int k0) {
    int sub = lane >> 3;
    int row = n0 + (lane & 7) + ((sub & 2) << 2);
    int kk  = k0 + ((sub & 1) << 3);
    return base + (row << 8) + ((((kk >> 3) ^ (row & 7)) & 15) << 4);
}

// acc[2][8][4] += 3-split product of x-tiles and W-tiles (one 128x64x128 slab)
__device__ __forceinline__ void gemm_split3(uint32_t sb, int lane, int wm, int wn,
                                            uint32_t offWh, uint32_t offWl,
                                            float acc[2][8][4]) {
#pragma unroll 1
    for (int k0 = 0; k0 < 128; k0 += 16) {
        uint32_t ah[2][4], al[2][4], bh[4][4], bl[4][4];
#pragma unroll
        for (int mt = 0; mt < 2; ++mt) {
            int r0 = wm * 32 + mt * 16;
            ldsm4(ah[mt], addrA(sb + SOFF_XH, lane, r0, k0));
            ldsm4(al[mt], addrA(sb + SOFF_XL, lane, r0, k0));
        }
#pragma unroll
        for (int nb = 0; nb < 4; ++nb) {
            int n0 = wn * 64 + nb * 16;
            ldsm4(bh[nb], addrB(sb + offWh, lane, n0, k0));
            ldsm4(bl[nb], addrB(sb + offWl, lane, n0, k0));
        }
#pragma unroll
        for (int mt = 0; mt < 2; ++mt)
#pragma unroll
            for (int nt = 0; nt < 8; ++nt) {
                const uint32_t* bph = &bh[nt >> 1][(nt & 1) << 1];
                const uint32_t* bpl = &bl[nt >> 1][(nt & 1) << 1];
                mma16816(acc[mt][nt], ah[mt], bph);   // xh * Whi
                mma16816(acc[mt][nt], ah[mt], bpl);   // xh * Wlo
                mma16816(acc[mt][nt], al[mt], bph);   // xl * Whi
            }
    }
}

// Split v (2 adjacent cols) into bf16 hi/lo and store into x tiles.
__device__ __forceinline__ void split_store(char* smem, int r, int c0, float va, float vb) {
    __nv_bfloat16 ha = __float2bfloat16(va), hb = __float2bfloat16(vb);
    float la = va - __bfloat162float(ha);
    float lb = vb - __bfloat162float(hb);
    uint32_t hi32 = ((uint32_t)__bfloat16_as_ushort(hb) << 16) | (uint32_t)__bfloat16_as_ushort(ha);
    uint32_t lo32 = ((uint32_t)__bfloat16_as_ushort(__float2bfloat16(lb)) << 16) |
                    (uint32_t)__bfloat16_as_ushort(__float2bfloat16(la));
    int off = swoff(r, c0);   // c0 even -> col c0+1 at off+2, same 4B word
    *(uint32_t*)(smem + SOFF_XH + off) = hi32;
    *(uint32_t*)(smem + SOFF_XL + off) = lo32;
}

__global__ void __launch_bounds__(256, 1) ffb_main(
    const float* __restrict__ in_pos,
    const float* __restrict__ gfeat,
    const float* __restrict__ W0,
    const float* __restrict__ b0,
    const float* __restrict__ b_mid,
    const float* __restrict__ b_high,
    float* __restrict__ out) {
    extern __shared__ char smem[];
    const uint32_t sb = smem_u32(smem);
    const int tid = threadIdx.x, wid = tid >> 5, lane = tid & 31;
    const int wm = wid & 3, wn = wid >> 2;      // 4 x 2 warp grid
    const int qr = lane >> 2, qc = lane & 3;
    const int p0 = blockIdx.x << 7;

    float* gxs = (float*)(smem + SOFF_GXS);
    float* bms = (float*)(smem + SOFF_BMS);
    float* bhs = (float*)(smem + SOFF_BHS);
    float* Asm = (float*)(smem + SOFF_ASM);

    // Stage per-CTA grid feats / biases / A
    for (int idx = tid; idx < 1792; idx += 256) {
        int m = idx / 14, c = idx - m * 14;
        gxs[idx] = gfeat[(size_t)(p0 + m) * 17 + 3 + c];
        Asm[idx] = g_As[idx];
    }
    for (int idx = tid; idx < 896; idx += 256) {
        bms[idx] = b_mid[idx];
        bhs[idx] = b_high[idx];
    }

    // pos01 outputs
    if (tid < 128) {
        size_t m = p0 + tid;
        float a = in_pos[m * 3 + 0], b = in_pos[m * 3 + 1], c = in_pos[m * 3 + 2];
        out[m * 131 + 0] = (a + 1.0f) * 0.5f;
        out[m * 131 + 1] = (b + 1.0f) * 0.5f;
        out[m * 131 + 2] = (c + 1.0f) * 0.5f;
    }

    // Layer 0: x = sin(56*(pos @ W0^T + b0)) -> split tiles
    for (int p = tid; p < 8192; p += 256) {
        int r = p >> 6, n = (p & 63) << 1;
        const float* pp = in_pos + (size_t)(p0 + r) * 3;
        float x0 = pp[0], x1 = pp[1], x2 = pp[2];
        float va = __sinf(W0S * (x0 * W0[n * 3 + 0] + x1 * W0[n * 3 + 1] + x2 * W0[n * 3 + 2] + b0[n]));
        float vb = __sinf(W0S * (x0 * W0[n * 3 + 3] + x1 * W0[n * 3 + 4] + x2 * W0[n * 3 + 5] + b0[n + 1]));
        split_store(smem, r, n, va, vb);
    }

    float buf[2][8][4];
#pragma unroll
    for (int a = 0; a < 2; ++a)
#pragma unroll
        for (int b = 0; b < 8; ++b)
#pragma unroll
            for (int c = 0; c < 4; ++c) buf[a][b][c] = 0.0f;

#pragma unroll 1
    for (int ly = 0; ly < LVL; ++ly) {
        __syncthreads();   // prior layer done with weight tiles & x tiles
        {   // stage 4 weight tiles (128 KB)
            const uint4* gmh = (const uint4*)(g_Wmh + ly * 32768);
            const uint4* gml = (const uint4*)(g_Wml + ly * 32768);
            const uint4* ghh = (const uint4*)(g_Whh + ly * 32768);
            const uint4* ghl = (const uint4*)(g_Whl + ly * 32768);
            uint4* smh = (uint4*)(smem + SOFF_WMH);
            uint4* sml = (uint4*)(smem + SOFF_WML);
            uint4* shh = (uint4*)(smem + SOFF_WHH);
            uint4* shl = (uint4*)(smem + SOFF_WHL);
#pragma unroll
            for (int t = 0; t < 8; ++t) {
                int i = tid + t * 256;
                smh[i] = gmh[i]; sml[i] = gml[i];
                shh[i] = ghh[i]; shl[i] = ghl[i];
            }
        }
        __syncthreads();

        // ---- mid GEMM ----
        float acc[2][8][4];
#pragma unroll
        for (int a = 0; a < 2; ++a)
#pragma unroll
            for (int b = 0; b < 8; ++b)
#pragma unroll
                for (int c = 0; c < 4; ++c) acc[a][b][c] = 0.0f;
        gemm_split3(sb, lane, wm, wn, SOFF_WMH, SOFF_WML, acc);
        __syncthreads();   // all warps done reading x tiles

        // ---- mid epilogue: x' = sin(56*(d+bm)) + sin(g.A) ----
#pragma unroll
        for (int mt = 0; mt < 2; ++mt) {
#pragma unroll
            for (int h = 0; h < 2; ++h) {
                int r = wm * 32 + mt * 16 + qr + (h << 3);
                float g0 = gxs[r * 14 + 2 * ly];
                float g1 = gxs[r * 14 + 2 * ly + 1];
#pragma unroll
                for (int nt = 0; nt < 8; ++nt) {
                    int c0 = wn * 64 + nt * 8 + 2 * qc;
                    float da = acc[mt][nt][2 * h];
                    float db = acc[mt][nt][2 * h + 1];
                    float va = __sinf(W0S * (da + bms[ly * 128 + c0])) +
                               __sinf(g0 * Asm[ly * 256 + c0] + g1 * Asm[ly * 256 + 128 + c0]);
                    float vb = __sinf(W0S * (db + bms[ly * 128 + c0 + 1])) +
                               __sinf(g0 * Asm[ly * 256 + c0 + 1] + g1 * Asm[ly * 256 + 129 + c0]);
                    split_store(smem, r, c0, va, vb);
                }
            }
        }
        __syncthreads();   // new x tiles visible

        // ---- high GEMM ----
#pragma unroll
        for (int a = 0; a < 2; ++a)
#pragma unroll
            for (int b = 0; b < 8; ++b)
#pragma unroll
                for (int c = 0; c < 4; ++c) acc[a][b][c] = 0.0f;
        gemm_split3(sb, lane, wm, wn, SOFF_WHH, SOFF_WHL, acc);

        // ---- high epilogue: buf += sin(56*(d+bh)) ----
#pragma unroll
        for (int mt = 0; mt < 2; ++mt)
#pragma unroll
            for (int nt = 0; nt < 8; ++nt) {
                int c0 = wn * 64 + nt * 8 + 2 * qc;
                float bb0 = bhs[ly * 128 + c0];
                float bb1 = bhs[ly * 128 + c0 + 1];
                buf[mt][nt][0] += __sinf(W0S * (acc[mt][nt][0] + bb0));
                buf[mt][nt][1] += __sinf(W0S * (acc[mt][nt][1] + bb1));
                buf[mt][nt][2] += __sinf(W0S * (acc[mt][nt][2] + bb0));
                buf[mt][nt][3] += __sinf(W0S * (acc[mt][nt][3] + bb1));
            }
    }

    // output
    const float inv7 = 1.0f / 7.0f;
#pragma unroll
    for (int mt = 0; mt < 2; ++mt)
#pragma unroll
        for (int h = 0; h < 2; ++h) {
            int r = wm * 32 + mt * 16 + qr + (h << 3);
            size_t base = (size_t)(p0 + r) * 131 + 3;
#pragma unroll
            for (int nt = 0; nt < 8; ++nt) {
                int c0 = wn * 64 + nt * 8 + 2 * qc;
                out[base + c0]     = buf[mt][nt][2 * h]     * inv7;
                out[base + c0 + 1] = buf[mt][nt][2 * h + 1] * inv7;
            }
        }
}

extern "C" void kernel_launch(void* const* d_in, const int* in_sizes, int n_in,
                              void* d_out, int out_size) {
    const float* in_pos = (const float*)d_in[0];
    const float* gfeat  = (const float*)d_in[1];
    const float* ffn_A  = (const float*)d_in[2];
    const float* sigma  = (const float*)d_in[3];
    const float* W0     = (const float*)d_in[4];
    const float* b0     = (const float*)d_in[5];
    const float* W_mid  = (const float*)d_in[6];
    const float* b_mid  = (const float*)d_in[7];
    const float* W_high = (const float*)d_in[8];
    const float* b_high = (const float*)d_in[9];
    float* out = (float*)d_out;

    int N = in_sizes[0] / 3;

    prep_kernel<<<448, 256>>>(W_mid, W_high, ffn_A, sigma);

    cudaFuncSetAttribute(ffb_main, cudaFuncAttributeMaxDynamicSharedMemorySize, SMEM_TOTAL);
    ffb_main<<<N / 128, 256, SMEM_TOTAL>>>(in_pos, gfeat, W0, b0, b_mid, b_high, out);
}

// round 4
// speedup vs baseline: 2.0463x; 1.0687x over previous
#include <cuda_runtime.h>
#include <cuda_bf16.h>
#include <cstdint>

#define LVL  7
#define W0S  56.0f

// SMEM byte offsets
#define SOFF_XH   0
#define SOFF_XL   32768
#define SOFF_WMH  65536
#define SOFF_WML  98304
#define SOFF_WHH  131072
#define SOFF_WHL  163840
#define SOFF_GXS  196608   // 1792 floats
#define SOFF_BMS  203776   // 896 floats
#define SOFF_BHS  207360   // 896 floats
#define SOFF_ASM  210944   // 1792 floats
#define SMEM_TOTAL 218112

// Pre-split, pre-swizzled bf16 weight tiles (n-major: W[n][k]).
__device__ __align__(16) char g_Wmh[LVL * 32768];
__device__ __align__(16) char g_Wml[LVL * 32768];
__device__ __align__(16) char g_Whh[LVL * 32768];
__device__ __align__(16) char g_Whl[LVL * 32768];
__device__ float g_As[LVL * 256];

// Byte offset of bf16 element (row r, col k) in a [128][128] bf16 tile.
__host__ __device__ __forceinline__ int swoff(int r, int k) {
    return (r << 8) + ((((k >> 3) ^ (r & 7)) & 15) << 4) + ((k & 7) << 1);
}

__global__ void prep_kernel(const float* __restrict__ Wm,
                            const float* __restrict__ Wh,
                            const float* __restrict__ A,
                            const float* __restrict__ sigma) {
    int i0 = blockIdx.x * blockDim.x + threadIdx.x;
    int stride = gridDim.x * blockDim.x;
    for (int idx = i0; idx < LVL * 16384; idx += stride) {
        int l = idx >> 14, rem = idx & 16383;
        int n = rem >> 7, k = rem & 127;
        int dst = l * 32768 + swoff(n, k);
        float wm = Wm[idx];
        __nv_bfloat16 hm = __float2bfloat16(wm);
        *(__nv_bfloat16*)(g_Wmh + dst) = hm;
        *(__nv_bfloat16*)(g_Wml + dst) = __float2bfloat16(wm - __bfloat162float(hm));
        float wh = Wh[idx];
        __nv_bfloat16 hh = __float2bfloat16(wh);
        *(__nv_bfloat16*)(g_Whh + dst) = hh;
        *(__nv_bfloat16*)(g_Whl + dst) = __float2bfloat16(wh - __bfloat162float(hh));
    }
    for (int idx = i0; idx < LVL * 256; idx += stride) {
        int l = idx >> 8;
        g_As[idx] = A[idx] * (6.28318530717958647692f * sigma[l]);
    }
}

__device__ __forceinline__ uint32_t smem_u32(const void* p) {
    uint32_t a;
    asm("{ .reg .u64 t; cvta.to.shared.u64 t, %1; cvt.u32.u64 %0, t; }" : "=r"(a) : "l"(p));
    return a;
}

__device__ __forceinline__ void cp16(uint32_t dst, const void* src) {
    asm volatile("cp.async.cg.shared.global [%0], [%1], 16;" :: "r"(dst), "l"(src));
}
#define CP_COMMIT() asm volatile("cp.async.commit_group;" ::: "memory")
#define CP_WAIT(N)  asm volatile("cp.async.wait_group %0;" :: "n"(N) : "memory")

__device__ __forceinline__ void ldsm4(uint32_t* r, uint32_t addr) {
    asm volatile("ldmatrix.sync.aligned.m8n8.x4.shared.b16 {%0,%1,%2,%3}, [%4];"
                 : "=r"(r[0]), "=r"(r[1]), "=r"(r[2]), "=r"(r[3]) : "r"(addr));
}

__device__ __forceinline__ void mma16816(float* d, const uint32_t* a, const uint32_t* b) {
    asm volatile(
        "mma.sync.aligned.m16n8k16.row.col.f32.bf16.bf16.f32 "
        "{%0,%1,%2,%3}, {%4,%5,%6,%7}, {%8,%9}, {%0,%1,%2,%3};"
        : "+f"(d[0]), "+f"(d[1]), "+f"(d[2]), "+f"(d[3])
        : "r"(a[0]), "r"(a[1]), "r"(a[2]), "r"(a[3]), "r"(b[0]), "r"(b[1]));
}

// lane address for A-tile ldmatrix.x4 covering (r0..r0+15, k0..k0+15)
__device__ __forceinline__ uint32_t addrA(uint32_t base, int lane, int r0, int k0) {
    int sub = lane >> 3;
    int row = r0 + (lane & 7) + ((sub & 1) << 3);
    int kk  = k0 + ((sub & 2) << 2);
    return base + (row << 8) + ((((kk >> 3) ^ (row & 7)) & 15) << 4);
}

// lane address for B-tile ldmatrix.x4 covering (n0..n0+15, k0..k0+15)
__device__ __forceinline__ uint32_t addrB(uint32_t base, int lane, int n0, int k0) {
    int sub = lane >> 3;
    int row = n0 + (lane & 7) + ((sub & 2) << 2);
    int kk  = k0 + ((sub & 1) << 3);
    return base + (row << 8) + ((((kk >> 3) ^ (row & 7)) & 15) << 4);
}

// acc[2][8][4] += 3-split product of x-tiles and W-tiles (one 128x64x128 slab)
__device__ __forceinline__ void gemm_split3(uint32_t sb, int lane, int wm, int wn,
                                            uint32_t offWh, uint32_t offWl,
                                            float acc[2][8][4]) {
#pragma unroll 1
    for (int k0 = 0; k0 < 128; k0 += 16) {
        uint32_t ah[2][4], al[2][4], bh[4][4], bl[4][4];
#pragma unroll
        for (int mt = 0; mt < 2; ++mt) {
            int r0 = wm * 32 + mt * 16;
            ldsm4(ah[mt], addrA(sb + SOFF_XH, lane, r0, k0));
            ldsm4(al[mt], addrA(sb + SOFF_XL, lane, r0, k0));
        }
#pragma unroll
        for (int nb = 0; nb < 4; ++nb) {
            int n0 = wn * 64 + nb * 16;
            ldsm4(bh[nb], addrB(sb + offWh, lane, n0, k0));
            ldsm4(bl[nb], addrB(sb + offWl, lane, n0, k0));
        }
#pragma unroll
        for (int mt = 0; mt < 2; ++mt)
#pragma unroll
            for (int nt = 0; nt < 8; ++nt) {
                const uint32_t* bph = &bh[nt >> 1][(nt & 1) << 1];
                const uint32_t* bpl = &bl[nt >> 1][(nt & 1) << 1];
                mma16816(acc[mt][nt], ah[mt], bph);   // xh * Whi
                mma16816(acc[mt][nt], ah[mt], bpl);   // xh * Wlo
                mma16816(acc[mt][nt], al[mt], bph);   // xl * Whi
            }
    }
}

// Split v (2 adjacent cols) into bf16 hi/lo and store into x tiles.
__device__ __forceinline__ void split_store(char* smem, int r, int c0, float va, float vb) {
    __nv_bfloat16 ha = __float2bfloat16(va), hb = __float2bfloat16(vb);
    float la = va - __bfloat162float(ha);
    float lb = vb - __bfloat162float(hb);
    uint32_t hi32 = ((uint32_t)__bfloat16_as_ushort(hb) << 16) | (uint32_t)__bfloat16_as_ushort(ha);
    uint32_t lo32 = ((uint32_t)__bfloat16_as_ushort(__float2bfloat16(lb)) << 16) |
                    (uint32_t)__bfloat16_as_ushort(__float2bfloat16(la));
    int off = swoff(r, c0);
    *(uint32_t*)(smem + SOFF_XH + off) = hi32;
    *(uint32_t*)(smem + SOFF_XL + off) = lo32;
}

// Issue the 16 cp.asyncs (hi+lo slabs) for one weight slot, layer ly.
__device__ __forceinline__ void prefetch_slot(uint32_t sb, int tid, int ly,
                                              uint32_t soff_hi, uint32_t soff_lo,
                                              const char* ghi, const char* glo) {
    const char* srch = ghi + ly * 32768;
    const char* srcl = glo + ly * 32768;
#pragma unroll
    for (int t = 0; t < 8; ++t) {
        int b = (tid + t * 256) * 16;
        cp16(sb + soff_hi + b, srch + b);
        cp16(sb + soff_lo + b, srcl + b);
    }
}

__global__ void __launch_bounds__(256, 1) ffb_main(
    const float* __restrict__ in_pos,
    const float* __restrict__ gfeat,
    const float* __restrict__ W0,
    const float* __restrict__ b0,
    const float* __restrict__ b_mid,
    const float* __restrict__ b_high,
    float* __restrict__ out) {
    extern __shared__ char smem[];
    const uint32_t sb = smem_u32(smem);
    const int tid = threadIdx.x, wid = tid >> 5, lane = tid & 31;
    const int wm = wid & 3, wn = wid >> 2;      // 4 x 2 warp grid
    const int qr = lane >> 2, qc = lane & 3;
    const int p0 = blockIdx.x << 7;

    float* gxs = (float*)(smem + SOFF_GXS);
    float* bms = (float*)(smem + SOFF_BMS);
    float* bhs = (float*)(smem + SOFF_BHS);
    float* Asm = (float*)(smem + SOFF_ASM);

    // Kick off layer-0 weight prefetch immediately (two groups: Gm0, Gh0).
    prefetch_slot(sb, tid, 0, SOFF_WMH, SOFF_WML, g_Wmh, g_Wml);
    CP_COMMIT();
    prefetch_slot(sb, tid, 0, SOFF_WHH, SOFF_WHL, g_Whh, g_Whl);
    CP_COMMIT();

    // Stage per-CTA grid feats / biases / A (overlaps with cp.async)
    for (int idx = tid; idx < 1792; idx += 256) {
        int m = idx / 14, c = idx - m * 14;
        gxs[idx] = gfeat[(size_t)(p0 + m) * 17 + 3 + c];
        Asm[idx] = g_As[idx];
    }
    for (int idx = tid; idx < 896; idx += 256) {
        bms[idx] = b_mid[idx];
        bhs[idx] = b_high[idx];
    }

    // pos01 outputs
    if (tid < 128) {
        size_t m = p0 + tid;
        float a = in_pos[m * 3 + 0], b = in_pos[m * 3 + 1], c = in_pos[m * 3 + 2];
        out[m * 131 + 0] = (a + 1.0f) * 0.5f;
        out[m * 131 + 1] = (b + 1.0f) * 0.5f;
        out[m * 131 + 2] = (c + 1.0f) * 0.5f;
    }

    // Layer 0: x = sin(56*(pos @ W0^T + b0)) -> split tiles
    for (int p = tid; p < 8192; p += 256) {
        int r = p >> 6, n = (p & 63) << 1;
        const float* pp = in_pos + (size_t)(p0 + r) * 3;
        float x0 = pp[0], x1 = pp[1], x2 = pp[2];
        float va = __sinf(W0S * (x0 * W0[n * 3 + 0] + x1 * W0[n * 3 + 1] + x2 * W0[n * 3 + 2] + b0[n]));
        float vb = __sinf(W0S * (x0 * W0[n * 3 + 3] + x1 * W0[n * 3 + 4] + x2 * W0[n * 3 + 5] + b0[n + 1]));
        split_store(smem, r, n, va, vb);
    }

    float buf[2][8][4];
#pragma unroll
    for (int a = 0; a < 2; ++a)
#pragma unroll
        for (int b = 0; b < 8; ++b)
#pragma unroll
            for (int c = 0; c < 4; ++c) buf[a][b][c] = 0.0f;

    CP_WAIT(1);        // Wm(0) arrived (Wh(0) may still be in flight)
    __syncthreads();   // publish x(0), Wm(0), staged tables

#pragma unroll 1
    for (int ly = 0; ly < LVL; ++ly) {
        // ---- mid GEMM (reads x(ly), Wm slot) ----
        float acc[2][8][4];
#pragma unroll
        for (int a = 0; a < 2; ++a)
#pragma unroll
            for (int b = 0; b < 8; ++b)
#pragma unroll
                for (int c = 0; c < 4; ++c) acc[a][b][c] = 0.0f;
        gemm_split3(sb, lane, wm, wn, SOFF_WMH, SOFF_WML, acc);
        __syncthreads();   // B1: x + Wm slot readers done

        if (ly < LVL - 1) {   // prefetch Wm(ly+1) into the now-free slot
            prefetch_slot(sb, tid, ly + 1, SOFF_WMH, SOFF_WML, g_Wmh, g_Wml);
            CP_COMMIT();
        }

        // ---- mid epilogue: x' = sin(56*(d+bm)) + sin(g.A) ----
#pragma unroll
        for (int mt = 0; mt < 2; ++mt) {
#pragma unroll
            for (int h = 0; h < 2; ++h) {
                int r = wm * 32 + mt * 16 + qr + (h << 3);
                float g0 = gxs[r * 14 + 2 * ly];
                float g1 = gxs[r * 14 + 2 * ly + 1];
#pragma unroll
                for (int nt = 0; nt < 8; ++nt) {
                    int c0 = wn * 64 + nt * 8 + 2 * qc;
                    float da = acc[mt][nt][2 * h];
                    float db = acc[mt][nt][2 * h + 1];
                    float va = __sinf(W0S * (da + bms[ly * 128 + c0])) +
                               __sinf(g0 * Asm[ly * 256 + c0] + g1 * Asm[ly * 256 + 128 + c0]);
                    float vb = __sinf(W0S * (db + bms[ly * 128 + c0 + 1])) +
                               __sinf(g0 * Asm[ly * 256 + c0 + 1] + g1 * Asm[ly * 256 + 129 + c0]);
                    split_store(smem, r, c0, va, vb);
                }
            }
        }

        CP_WAIT(1);        // oldest pending (Wh(ly)) complete
        __syncthreads();   // B2: x(ly+1) + Wh(ly) visible

        // ---- high GEMM (reads x(ly+1), Wh slot) ----
#pragma unroll
        for (int a = 0; a < 2; ++a)
#pragma unroll
            for (int b = 0; b < 8; ++b)
#pragma unroll
                for (int c = 0; c < 4; ++c) acc[a][b][c] = 0.0f;
        gemm_split3(sb, lane, wm, wn, SOFF_WHH, SOFF_WHL, acc);

        // ---- high epilogue: buf += sin(56*(d+bh)) ----
#pragma unroll
        for (int mt = 0; mt < 2; ++mt)
#pragma unroll
            for (int nt = 0; nt < 8; ++nt) {
                int c0 = wn * 64 + nt * 8 + 2 * qc;
                float bb0 = bhs[ly * 128 + c0];
                float bb1 = bhs[ly * 128 + c0 + 1];
                buf[mt][nt][0] += __sinf(W0S * (acc[mt][nt][0] + bb0));
                buf[mt][nt][1] += __sinf(W0S * (acc[mt][nt][1] + bb1));
                buf[mt][nt][2] += __sinf(W0S * (acc[mt][nt][2] + bb0));
                buf[mt][nt][3] += __sinf(W0S * (acc[mt][nt][3] + bb1));
            }

        CP_WAIT(0);        // Wm(ly+1) complete (only remaining group)
        __syncthreads();   // B3: Wh slot free + Wm(ly+1) published

        if (ly < LVL - 1) {   // prefetch Wh(ly+1); waited at next B2
            prefetch_slot(sb, tid, ly + 1, SOFF_WHH, SOFF_WHL, g_Whh, g_Whl);
            CP_COMMIT();
        }
    }

    // output
    const float inv7 = 1.0f / 7.0f;
#pragma unroll
    for (int mt = 0; mt < 2; ++mt)
#pragma unroll
        for (int h = 0; h < 2; ++h) {
            int r = wm * 32 + mt * 16 + qr + (h << 3);
            size_t base = (size_t)(p0 + r) * 131 + 3;
#pragma unroll
            for (int nt = 0; nt < 8; ++nt) {
                int c0 = wn * 64 + nt * 8 + 2 * qc;
                out[base + c0]     = buf[mt][nt][2 * h]     * inv7;
                out[base + c0 + 1] = buf[mt][nt][2 * h + 1] * inv7;
            }
        }
}

extern "C" void kernel_launch(void* const* d_in, const int* in_sizes, int n_in,
                              void* d_out, int out_size) {
    const float* in_pos = (const float*)d_in[0];
    const float* gfeat  = (const float*)d_in[1];
    const float* ffn_A  = (const float*)d_in[2];
    const float* sigma  = (const float*)d_in[3];
    const float* W0     = (const float*)d_in[4];
    const float* b0     = (const float*)d_in[5];
    const float* W_mid  = (const float*)d_in[6];
    const float* b_mid  = (const float*)d_in[7];
    const float* W_high = (const float*)d_in[8];
    const float* b_high = (const float*)d_in[9];
    float* out = (float*)d_out;

    int N = in_sizes[0] / 3;

    prep_kernel<<<448, 256>>>(W_mid, W_high, ffn_A, sigma);

    cudaFuncSetAttribute(ffb_main, cudaFuncAttributeMaxDynamicSharedMemorySize, SMEM_TOTAL);
    ffb_main<<<N / 128, 256, SMEM_TOTAL>>>(in_pos, gfeat, W0, b0, b_mid, b_high, out);
}

// round 5
// speedup vs baseline: 2.2011x; 1.0756x over previous
#include <cuda_runtime.h>
#include <cuda_bf16.h>
#include <cstdint>

#define LVL  7
#define W0S  56.0f
#define NT   512

// SMEM byte offsets
#define SOFF_XH   0
#define SOFF_XL   32768
#define SOFF_WMH  65536
#define SOFF_WML  98304
#define SOFF_WHH  131072
#define SOFF_WHL  163840
#define SOFF_GXS  196608   // 1792 floats
#define SOFF_BMS  203776   // 896 floats
#define SOFF_BHS  207360   // 896 floats
#define SOFF_ASM  210944   // 1792 floats
#define SMEM_TOTAL 218112

// Pre-split, pre-swizzled bf16 weight tiles (n-major: W[n][k]).
__device__ __align__(16) char g_Wmh[LVL * 32768];
__device__ __align__(16) char g_Wml[LVL * 32768];
__device__ __align__(16) char g_Whh[LVL * 32768];
__device__ __align__(16) char g_Whl[LVL * 32768];
__device__ float g_As[LVL * 256];

// Byte offset of bf16 element (row r, col k) in a [128][128] bf16 tile.
__host__ __device__ __forceinline__ int swoff(int r, int k) {
    return (r << 8) + ((((k >> 3) ^ (r & 7)) & 15) << 4) + ((k & 7) << 1);
}

__global__ void prep_kernel(const float* __restrict__ Wm,
                            const float* __restrict__ Wh,
                            const float* __restrict__ A,
                            const float* __restrict__ sigma) {
    int i0 = blockIdx.x * blockDim.x + threadIdx.x;
    int stride = gridDim.x * blockDim.x;
    for (int idx = i0; idx < LVL * 16384; idx += stride) {
        int l = idx >> 14, rem = idx & 16383;
        int n = rem >> 7, k = rem & 127;
        int dst = l * 32768 + swoff(n, k);
        float wm = Wm[idx];
        __nv_bfloat16 hm = __float2bfloat16(wm);
        *(__nv_bfloat16*)(g_Wmh + dst) = hm;
        *(__nv_bfloat16*)(g_Wml + dst) = __float2bfloat16(wm - __bfloat162float(hm));
        float wh = Wh[idx];
        __nv_bfloat16 hh = __float2bfloat16(wh);
        *(__nv_bfloat16*)(g_Whh + dst) = hh;
        *(__nv_bfloat16*)(g_Whl + dst) = __float2bfloat16(wh - __bfloat162float(hh));
    }
    for (int idx = i0; idx < LVL * 256; idx += stride) {
        int l = idx >> 8;
        g_As[idx] = A[idx] * (6.28318530717958647692f * sigma[l]);
    }
}

__device__ __forceinline__ uint32_t smem_u32(const void* p) {
    uint32_t a;
    asm("{ .reg .u64 t; cvta.to.shared.u64 t, %1; cvt.u32.u64 %0, t; }" : "=r"(a) : "l"(p));
    return a;
}

__device__ __forceinline__ void cp16(uint32_t dst, const void* src) {
    asm volatile("cp.async.cg.shared.global [%0], [%1], 16;" :: "r"(dst), "l"(src));
}
#define CP_COMMIT() asm volatile("cp.async.commit_group;" ::: "memory")
#define CP_WAIT(N)  asm volatile("cp.async.wait_group %0;" :: "n"(N) : "memory")

__device__ __forceinline__ void ldsm4(uint32_t* r, uint32_t addr) {
    asm volatile("ldmatrix.sync.aligned.m8n8.x4.shared.b16 {%0,%1,%2,%3}, [%4];"
                 : "=r"(r[0]), "=r"(r[1]), "=r"(r[2]), "=r"(r[3]) : "r"(addr));
}

__device__ __forceinline__ void mma16816(float* d, const uint32_t* a, const uint32_t* b) {
    asm volatile(
        "mma.sync.aligned.m16n8k16.row.col.f32.bf16.bf16.f32 "
        "{%0,%1,%2,%3}, {%4,%5,%6,%7}, {%8,%9}, {%0,%1,%2,%3};"
        : "+f"(d[0]), "+f"(d[1]), "+f"(d[2]), "+f"(d[3])
        : "r"(a[0]), "r"(a[1]), "r"(a[2]), "r"(a[3]), "r"(b[0]), "r"(b[1]));
}

// lane address for A-tile ldmatrix.x4 covering (r0..r0+15, k0..k0+15)
__device__ __forceinline__ uint32_t addrA(uint32_t base, int lane, int r0, int k0) {
    int sub = lane >> 3;
    int row = r0 + (lane & 7) + ((sub & 1) << 3);
    int kk  = k0 + ((sub & 2) << 2);
    return base + (row << 8) + ((((kk >> 3) ^ (row & 7)) & 15) << 4);
}

// lane address for B-tile ldmatrix.x4 covering (n0..n0+15, k0..k0+15)
__device__ __forceinline__ uint32_t addrB(uint32_t base, int lane, int n0, int k0) {
    int sub = lane >> 3;
    int row = n0 + (lane & 7) + ((sub & 2) << 2);
    int kk  = k0 + ((sub & 1) << 3);
    return base + (row << 8) + ((((kk >> 3) ^ (row & 7)) & 15) << 4);
}

// acc[2][4][4] += 3-split product: warp tile 32M x 32N, full K=128.
__device__ __forceinline__ void gemm_split3(uint32_t sb, int lane, int wm, int wn,
                                            uint32_t offWh, uint32_t offWl,
                                            float acc[2][4][4]) {
#pragma unroll 1
    for (int k0 = 0; k0 < 128; k0 += 16) {
        uint32_t ah[2][4], al[2][4], bh[2][4], bl[2][4];
#pragma unroll
        for (int mt = 0; mt < 2; ++mt) {
            int r0 = wm * 32 + mt * 16;
            ldsm4(ah[mt], addrA(sb + SOFF_XH, lane, r0, k0));
            ldsm4(al[mt], addrA(sb + SOFF_XL, lane, r0, k0));
        }
#pragma unroll
        for (int nb = 0; nb < 2; ++nb) {
            int n0 = wn * 32 + nb * 16;
            ldsm4(bh[nb], addrB(sb + offWh, lane, n0, k0));
            ldsm4(bl[nb], addrB(sb + offWl, lane, n0, k0));
        }
#pragma unroll
        for (int mt = 0; mt < 2; ++mt)
#pragma unroll
            for (int nt = 0; nt < 4; ++nt) {
                const uint32_t* bph = &bh[nt >> 1][(nt & 1) << 1];
                const uint32_t* bpl = &bl[nt >> 1][(nt & 1) << 1];
                mma16816(acc[mt][nt], ah[mt], bph);   // xh * Whi
                mma16816(acc[mt][nt], ah[mt], bpl);   // xh * Wlo
                mma16816(acc[mt][nt], al[mt], bph);   // xl * Whi
            }
    }
}

// Split v (2 adjacent cols) into bf16 hi/lo and store into x tiles.
__device__ __forceinline__ void split_store(char* smem, int r, int c0, float va, float vb) {
    __nv_bfloat16 ha = __float2bfloat16(va), hb = __float2bfloat16(vb);
    float la = va - __bfloat162float(ha);
    float lb = vb - __bfloat162float(hb);
    uint32_t hi32 = ((uint32_t)__bfloat16_as_ushort(hb) << 16) | (uint32_t)__bfloat16_as_ushort(ha);
    uint32_t lo32 = ((uint32_t)__bfloat16_as_ushort(__float2bfloat16(lb)) << 16) |
                    (uint32_t)__bfloat16_as_ushort(__float2bfloat16(la));
    int off = swoff(r, c0);
    *(uint32_t*)(smem + SOFF_XH + off) = hi32;
    *(uint32_t*)(smem + SOFF_XL + off) = lo32;
}

// Issue cp.asyncs (hi+lo slabs) for one weight slot, layer ly. 512 threads.
__device__ __forceinline__ void prefetch_slot(uint32_t sb, int tid, int ly,
                                              uint32_t soff_hi, uint32_t soff_lo,
                                              const char* ghi, const char* glo) {
    const char* srch = ghi + ly * 32768;
    const char* srcl = glo + ly * 32768;
#pragma unroll
    for (int t = 0; t < 4; ++t) {
        int b = (tid + t * NT) * 16;
        cp16(sb + soff_hi + b, srch + b);
        cp16(sb + soff_lo + b, srcl + b);
    }
}

__global__ void __launch_bounds__(NT, 1) ffb_main(
    const float* __restrict__ in_pos,
    const float* __restrict__ gfeat,
    const float* __restrict__ W0,
    const float* __restrict__ b0,
    const float* __restrict__ b_mid,
    const float* __restrict__ b_high,
    float* __restrict__ out) {
    extern __shared__ char smem[];
    const uint32_t sb = smem_u32(smem);
    const int tid = threadIdx.x, wid = tid >> 5, lane = tid & 31;
    const int wm = wid & 3, wn = wid >> 2;      // 4 x 4 warp grid
    const int qr = lane >> 2, qc = lane & 3;
    const int p0 = blockIdx.x << 7;

    float* gxs = (float*)(smem + SOFF_GXS);
    float* bms = (float*)(smem + SOFF_BMS);
    float* bhs = (float*)(smem + SOFF_BHS);
    float* Asm = (float*)(smem + SOFF_ASM);

    // Kick off layer-0 weight prefetch immediately (two groups: Gm0, Gh0).
    prefetch_slot(sb, tid, 0, SOFF_WMH, SOFF_WML, g_Wmh, g_Wml);
    CP_COMMIT();
    prefetch_slot(sb, tid, 0, SOFF_WHH, SOFF_WHL, g_Whh, g_Whl);
    CP_COMMIT();

    // Stage per-CTA grid feats / biases / A (overlaps with cp.async)
    for (int idx = tid; idx < 1792; idx += NT) {
        int m = idx / 14, c = idx - m * 14;
        gxs[idx] = gfeat[(size_t)(p0 + m) * 17 + 3 + c];
        Asm[idx] = g_As[idx];
    }
    for (int idx = tid; idx < 896; idx += NT) {
        bms[idx] = b_mid[idx];
        bhs[idx] = b_high[idx];
    }

    // pos01 outputs
    if (tid < 128) {
        size_t m = p0 + tid;
        float a = in_pos[m * 3 + 0], b = in_pos[m * 3 + 1], c = in_pos[m * 3 + 2];
        out[m * 131 + 0] = (a + 1.0f) * 0.5f;
        out[m * 131 + 1] = (b + 1.0f) * 0.5f;
        out[m * 131 + 2] = (c + 1.0f) * 0.5f;
    }

    // Layer 0: x = sin(56*(pos @ W0^T + b0)) -> split tiles
    for (int p = tid; p < 8192; p += NT) {
        int r = p >> 6, n = (p & 63) << 1;
        const float* pp = in_pos + (size_t)(p0 + r) * 3;
        float x0 = pp[0], x1 = pp[1], x2 = pp[2];
        float va = __sinf(W0S * (x0 * W0[n * 3 + 0] + x1 * W0[n * 3 + 1] + x2 * W0[n * 3 + 2] + b0[n]));
        float vb = __sinf(W0S * (x0 * W0[n * 3 + 3] + x1 * W0[n * 3 + 4] + x2 * W0[n * 3 + 5] + b0[n + 1]));
        split_store(smem, r, n, va, vb);
    }

    float buf[2][4][4];
#pragma unroll
    for (int a = 0; a < 2; ++a)
#pragma unroll
        for (int b = 0; b < 4; ++b)
#pragma unroll
            for (int c = 0; c < 4; ++c) buf[a][b][c] = 0.0f;

    CP_WAIT(1);        // Wm(0) arrived (Wh(0) may still be in flight)
    __syncthreads();   // publish x(0), Wm(0), staged tables

#pragma unroll 1
    for (int ly = 0; ly < LVL; ++ly) {
        // ---- mid GEMM (reads x(ly), Wm slot) ----
        float acc[2][4][4];
#pragma unroll
        for (int a = 0; a < 2; ++a)
#pragma unroll
            for (int b = 0; b < 4; ++b)
#pragma unroll
                for (int c = 0; c < 4; ++c) acc[a][b][c] = 0.0f;
        gemm_split3(sb, lane, wm, wn, SOFF_WMH, SOFF_WML, acc);
        __syncthreads();   // B1: x + Wm slot readers done

        if (ly < LVL - 1) {   // prefetch Wm(ly+1) into the now-free slot
            prefetch_slot(sb, tid, ly + 1, SOFF_WMH, SOFF_WML, g_Wmh, g_Wml);
            CP_COMMIT();
        }

        // ---- mid epilogue: x' = sin(56*(d+bm)) + sin(g.A) ----
#pragma unroll
        for (int mt = 0; mt < 2; ++mt) {
#pragma unroll
            for (int h = 0; h < 2; ++h) {
                int r = wm * 32 + mt * 16 + qr + (h << 3);
                float g0 = gxs[r * 14 + 2 * ly];
                float g1 = gxs[r * 14 + 2 * ly + 1];
#pragma unroll
                for (int nt = 0; nt < 4; ++nt) {
                    int c0 = wn * 32 + nt * 8 + 2 * qc;
                    float da = acc[mt][nt][2 * h];
                    float db = acc[mt][nt][2 * h + 1];
                    float va = __sinf(W0S * (da + bms[ly * 128 + c0])) +
                               __sinf(g0 * Asm[ly * 256 + c0] + g1 * Asm[ly * 256 + 128 + c0]);
                    float vb = __sinf(W0S * (db + bms[ly * 128 + c0 + 1])) +
                               __sinf(g0 * Asm[ly * 256 + c0 + 1] + g1 * Asm[ly * 256 + 129 + c0]);
                    split_store(smem, r, c0, va, vb);
                }
            }
        }

        CP_WAIT(1);        // oldest pending (Wh(ly)) complete
        __syncthreads();   // B2: x(ly+1) + Wh(ly) visible

        // ---- high GEMM (reads x(ly+1), Wh slot) ----
#pragma unroll
        for (int a = 0; a < 2; ++a)
#pragma unroll
            for (int b = 0; b < 4; ++b)
#pragma unroll
                for (int c = 0; c < 4; ++c) acc[a][b][c] = 0.0f;
        gemm_split3(sb, lane, wm, wn, SOFF_WHH, SOFF_WHL, acc);

        // ---- high epilogue: buf += sin(56*(d+bh)) ----
#pragma unroll
        for (int mt = 0; mt < 2; ++mt)
#pragma unroll
            for (int nt = 0; nt < 4; ++nt) {
                int c0 = wn * 32 + nt * 8 + 2 * qc;
                float bb0 = bhs[ly * 128 + c0];
                float bb1 = bhs[ly * 128 + c0 + 1];
                buf[mt][nt][0] += __sinf(W0S * (acc[mt][nt][0] + bb0));
                buf[mt][nt][1] += __sinf(W0S * (acc[mt][nt][1] + bb1));
                buf[mt][nt][2] += __sinf(W0S * (acc[mt][nt][2] + bb0));
                buf[mt][nt][3] += __sinf(W0S * (acc[mt][nt][3] + bb1));
            }

        CP_WAIT(0);        // Wm(ly+1) complete (only remaining group)
        __syncthreads();   // B3: Wh slot free + Wm(ly+1) published

        if (ly < LVL - 1) {   // prefetch Wh(ly+1); waited at next B2
            prefetch_slot(sb, tid, ly + 1, SOFF_WHH, SOFF_WHL, g_Whh, g_Whl);
            CP_COMMIT();
        }
    }

    // output
    const float inv7 = 1.0f / 7.0f;
#pragma unroll
    for (int mt = 0; mt < 2; ++mt)
#pragma unroll
        for (int h = 0; h < 2; ++h) {
            int r = wm * 32 + mt * 16 + qr + (h << 3);
            size_t base = (size_t)(p0 + r) * 131 + 3;
#pragma unroll
            for (int nt = 0; nt < 4; ++nt) {
                int c0 = wn * 32 + nt * 8 + 2 * qc;
                out[base + c0]     = buf[mt][nt][2 * h]     * inv7;
                out[base + c0 + 1] = buf[mt][nt][2 * h + 1] * inv7;
            }
        }
}

extern "C" void kernel_launch(void* const* d_in, const int* in_sizes, int n_in,
                              void* d_out, int out_size) {
    const float* in_pos = (const float*)d_in[0];
    const float* gfeat  = (const float*)d_in[1];
    const float* ffn_A  = (const float*)d_in[2];
    const float* sigma  = (const float*)d_in[3];
    const float* W0     = (const float*)d_in[4];
    const float* b0     = (const float*)d_in[5];
    const float* W_mid  = (const float*)d_in[6];
    const float* b_mid  = (const float*)d_in[7];
    const float* W_high = (const float*)d_in[8];
    const float* b_high = (const float*)d_in[9];
    float* out = (float*)d_out;

    int N = in_sizes[0] / 3;

    prep_kernel<<<448, 256>>>(W_mid, W_high, ffn_A, sigma);

    cudaFuncSetAttribute(ffb_main, cudaFuncAttributeMaxDynamicSharedMemorySize, SMEM_TOTAL);
    ffb_main<<<N / 128, NT, SMEM_TOTAL>>>(in_pos, gfeat, W0, b0, b_mid, b_high, out);
}